// round 6
// baseline (speedup 1.0000x reference)
#include <cuda_runtime.h>
#include <cstddef>

#define NA 20000
#define NP 40000
#define EE 400000
#define HID 128
#define NCLS 16

// ----------------------------- scratch (static device globals) -------------------
// Arena: everything that must be zeroed per layer, contiguous -> ONE memset.
//   [0)              denom slot0 (NP*8)
//   [NP*8)           denom slot1 (NP*8)
//   [2*NP*8)         denom slot2 (NP*8)
//   [3*NP*8)         aggP0 (NP*128)
//   [.. + NP*128)    aggP1 (NP*128)
//   [.. + NP*128)    colsum (256)
#define AR_DEN0   0
#define AR_AGGP0  (3 * NP * 8)
#define AR_AGGP1  (AR_AGGP0 + NP * HID)
#define AR_COLSUM (AR_AGGP1 + NP * HID)
#define AR_TOTAL  (AR_COLSUM + 256)

__device__ float g_arena[AR_TOTAL];
__device__ float g_aggA[NA * HID];          // author aggregation (zeroed at l=0 only)
__device__ float g_auth0[NA * HID];         // x_author @ Wa
__device__ float g_pap[NP * HID];           // paper features after layer-0 combine
__device__ float g_xa[NA * HID];            // xh author
__device__ float g_xp[NP * HID];            // xh paper
__device__ float g_escr0[(size_t)EE * 8];
__device__ float g_escr1[(size_t)EE * 8];
__device__ float g_escr2[(size_t)EE * 8];
__device__ float g_sa0[NA * 8];             // author: writes-src
__device__ float g_sa1[NA * 8];             // author: written_by-dst
__device__ float g_sp0[NP * 8];             // paper: writes-dst
__device__ float g_sp1[NP * 8];             // paper: written_by-src
__device__ float g_sp2[NP * 8];             // paper: cites-src
__device__ float g_sp3[NP * 8];             // paper: cites-dst
__device__ float g_attn[2];
__device__ float g_zb[HID];                 // zero bias

// ----------------------------- helpers -------------------------------------------
__device__ __forceinline__ void atomic_add_f4(float4* addr, float4 v) {
#if __CUDA_ARCH__ >= 900
    atomicAdd(addr, v);
#else
    float* f = (float*)addr;
    atomicAdd(f + 0, v.x); atomicAdd(f + 1, v.y);
    atomicAdd(f + 2, v.z); atomicAdd(f + 3, v.w);
#endif
}

struct SC { const float* att; float* out; };
struct SCSet { SC s[4]; int n; };

// ----------------------------- GEMM: C[Mx128] = (relu?)A[MxK] @ B[Kx128] + bias ----
// Epilogue also emits up to 4 per-node/per-head attention scores:
//   out[n*8+h] = dot(C[n, 16h:16h+16], att[16h:16h+16])
template <bool RELUA>
__global__ __launch_bounds__(256, 2)
void gemm128(const float* __restrict__ A, const float* __restrict__ B,
             const float* __restrict__ bias, float* __restrict__ C,
             int M, int K, SCSet sc)
{
    __shared__ alignas(16) float As[16][132];
    __shared__ alignas(16) float Bs[16][132];

    const int tid = threadIdx.x;
    const int tx = tid & 15;
    const int ty = tid >> 4;
    const int block_row = blockIdx.x * 128;

    const int a_row  = tid >> 1;
    const int a_col0 = (tid & 1) * 8;
    const int b_row  = tid >> 4;          // 0..15
    const int b_col  = (tid & 15) * 8;

    float acc[8][8];
#pragma unroll
    for (int i = 0; i < 8; i++)
#pragma unroll
        for (int j = 0; j < 8; j++) acc[i][j] = 0.f;

    for (int k0 = 0; k0 < K; k0 += 16) {
        const int gr = block_row + a_row;
        float4 av0 = make_float4(0.f, 0.f, 0.f, 0.f);
        float4 av1 = av0;
        if (gr < M) {
            av0 = *(const float4*)(A + (size_t)gr * K + k0 + a_col0);
            av1 = *(const float4*)(A + (size_t)gr * K + k0 + a_col0 + 4);
        }
        if constexpr (RELUA) {
            av0.x = fmaxf(av0.x, 0.f); av0.y = fmaxf(av0.y, 0.f);
            av0.z = fmaxf(av0.z, 0.f); av0.w = fmaxf(av0.w, 0.f);
            av1.x = fmaxf(av1.x, 0.f); av1.y = fmaxf(av1.y, 0.f);
            av1.z = fmaxf(av1.z, 0.f); av1.w = fmaxf(av1.w, 0.f);
        }
        As[a_col0 + 0][a_row] = av0.x; As[a_col0 + 1][a_row] = av0.y;
        As[a_col0 + 2][a_row] = av0.z; As[a_col0 + 3][a_row] = av0.w;
        As[a_col0 + 4][a_row] = av1.x; As[a_col0 + 5][a_row] = av1.y;
        As[a_col0 + 6][a_row] = av1.z; As[a_col0 + 7][a_row] = av1.w;

        *(float4*)&Bs[b_row][b_col] =
            *(const float4*)(B + (size_t)(k0 + b_row) * 128 + b_col);
        *(float4*)&Bs[b_row][b_col + 4] =
            *(const float4*)(B + (size_t)(k0 + b_row) * 128 + b_col + 4);
        __syncthreads();

#pragma unroll
        for (int k = 0; k < 16; k++) {
            float4 a0 = *(const float4*)&As[k][ty * 8];
            float4 a1 = *(const float4*)&As[k][ty * 8 + 4];
            float4 b0 = *(const float4*)&Bs[k][tx * 8];
            float4 b1 = *(const float4*)&Bs[k][tx * 8 + 4];
            float ar[8] = {a0.x, a0.y, a0.z, a0.w, a1.x, a1.y, a1.z, a1.w};
            float br[8] = {b0.x, b0.y, b0.z, b0.w, b1.x, b1.y, b1.z, b1.w};
#pragma unroll
            for (int i = 0; i < 8; i++)
#pragma unroll
                for (int j = 0; j < 8; j++)
                    acc[i][j] = fmaf(ar[i], br[j], acc[i][j]);
        }
        __syncthreads();
    }

    float bc[8];
#pragma unroll
    for (int j = 0; j < 8; j++) bc[j] = __ldg(&bias[tx * 8 + j]);
#pragma unroll
    for (int i = 0; i < 8; i++)
#pragma unroll
        for (int j = 0; j < 8; j++) acc[i][j] += bc[j];

#pragma unroll
    for (int i = 0; i < 8; i++) {
        const int r = block_row + ty * 8 + i;
        if (r < M) {
            *(float4*)(C + (size_t)r * 128 + tx * 8) =
                make_float4(acc[i][0], acc[i][1], acc[i][2], acc[i][3]);
            *(float4*)(C + (size_t)r * 128 + tx * 8 + 4) =
                make_float4(acc[i][4], acc[i][5], acc[i][6], acc[i][7]);
        }
    }

    // fused attention-score epilogue
    for (int s = 0; s < sc.n; s++) {
        const float* av = sc.s[s].att;
        float* o = sc.s[s].out;
        float4 q0 = __ldg((const float4*)(av + tx * 8));
        float4 q1 = __ldg((const float4*)(av + tx * 8 + 4));
        float qr[8] = {q0.x, q0.y, q0.z, q0.w, q1.x, q1.y, q1.z, q1.w};
#pragma unroll
        for (int i = 0; i < 8; i++) {
            float p = 0.f;
#pragma unroll
            for (int j = 0; j < 8; j++) p = fmaf(acc[i][j], qr[j], p);
            p += __shfl_xor_sync(0xffffffffu, p, 1);
            const int r = block_row + ty * 8 + i;
            if (((tx & 1) == 0) && r < M) o[(size_t)r * 8 + (tx >> 1)] = p;
        }
    }
}

// ----------------------------- tanh-colsum GEMM (semantic attention) ---------------
// colsum[y*128 + c] += sum_rows tanh( (relu(A_y) @ B + bias)[r,c] );  y = metapath
__global__ __launch_bounds__(256, 2)
void gemm_tanh(const float* __restrict__ A0, const float* __restrict__ A1,
               const float* __restrict__ B, const float* __restrict__ bias,
               float* __restrict__ colsum, int M)
{
    __shared__ alignas(16) float As[16][132];
    __shared__ alignas(16) float Bs[16][132];

    const float* A = blockIdx.y ? A1 : A0;
    float* cs = colsum + blockIdx.y * 128;

    const int tid = threadIdx.x;
    const int tx = tid & 15;
    const int ty = tid >> 4;
    const int block_row = blockIdx.x * 128;

    const int a_row  = tid >> 1;
    const int a_col0 = (tid & 1) * 8;
    const int b_row  = tid >> 4;
    const int b_col  = (tid & 15) * 8;

    float acc[8][8];
#pragma unroll
    for (int i = 0; i < 8; i++)
#pragma unroll
        for (int j = 0; j < 8; j++) acc[i][j] = 0.f;

    for (int k0 = 0; k0 < 128; k0 += 16) {
        const int gr = block_row + a_row;
        float4 av0 = make_float4(0.f, 0.f, 0.f, 0.f);
        float4 av1 = av0;
        if (gr < M) {
            av0 = *(const float4*)(A + (size_t)gr * 128 + k0 + a_col0);
            av1 = *(const float4*)(A + (size_t)gr * 128 + k0 + a_col0 + 4);
        }
        av0.x = fmaxf(av0.x, 0.f); av0.y = fmaxf(av0.y, 0.f);
        av0.z = fmaxf(av0.z, 0.f); av0.w = fmaxf(av0.w, 0.f);
        av1.x = fmaxf(av1.x, 0.f); av1.y = fmaxf(av1.y, 0.f);
        av1.z = fmaxf(av1.z, 0.f); av1.w = fmaxf(av1.w, 0.f);
        As[a_col0 + 0][a_row] = av0.x; As[a_col0 + 1][a_row] = av0.y;
        As[a_col0 + 2][a_row] = av0.z; As[a_col0 + 3][a_row] = av0.w;
        As[a_col0 + 4][a_row] = av1.x; As[a_col0 + 5][a_row] = av1.y;
        As[a_col0 + 6][a_row] = av1.z; As[a_col0 + 7][a_row] = av1.w;

        *(float4*)&Bs[b_row][b_col] =
            *(const float4*)(B + (size_t)(k0 + b_row) * 128 + b_col);
        *(float4*)&Bs[b_row][b_col + 4] =
            *(const float4*)(B + (size_t)(k0 + b_row) * 128 + b_col + 4);
        __syncthreads();

#pragma unroll
        for (int k = 0; k < 16; k++) {
            float4 a0 = *(const float4*)&As[k][ty * 8];
            float4 a1 = *(const float4*)&As[k][ty * 8 + 4];
            float4 b0 = *(const float4*)&Bs[k][tx * 8];
            float4 b1 = *(const float4*)&Bs[k][tx * 8 + 4];
            float ar[8] = {a0.x, a0.y, a0.z, a0.w, a1.x, a1.y, a1.z, a1.w};
            float br[8] = {b0.x, b0.y, b0.z, b0.w, b1.x, b1.y, b1.z, b1.w};
#pragma unroll
            for (int i = 0; i < 8; i++)
#pragma unroll
                for (int j = 0; j < 8; j++)
                    acc[i][j] = fmaf(ar[i], br[j], acc[i][j]);
        }
        __syncthreads();
    }

    float bc[8];
#pragma unroll
    for (int j = 0; j < 8; j++) bc[j] = __ldg(&bias[tx * 8 + j]);

    __shared__ float red[128];
    if (tid < 128) red[tid] = 0.f;
    __syncthreads();
    float csr[8];
#pragma unroll
    for (int j = 0; j < 8; j++) csr[j] = 0.f;
#pragma unroll
    for (int i = 0; i < 8; i++) {
        const int r = block_row + ty * 8 + i;
        if (r < M) {
#pragma unroll
            for (int j = 0; j < 8; j++)
                csr[j] += tanhf(acc[i][j] + bc[j]);
        }
    }
#pragma unroll
    for (int j = 0; j < 8; j++) atomicAdd(&red[tx * 8 + j], csr[j]);
    __syncthreads();
    if (tid < 128) atomicAdd(&cs[tid], red[tid]);
}

// ----------------------------- edge pass A (all edge types, blockIdx.y) -----------
struct PA {
    const int* ei[3];
    const float* asc[3];
    const float* adc[3];
    float* escr[3];
    float* den[3];
};

__global__ void passA_k(PA p)
{
    const int y = blockIdx.y;
    const int e = blockIdx.x * blockDim.x + threadIdx.x;
    if (e >= EE) return;
    const int* ei = p.ei[y];
    const int si = __ldg(&ei[e]);
    const int di = __ldg(&ei[EE + e]);
    const float4* sp = (const float4*)(p.asc[y] + (size_t)si * 8);
    const float4* dp = (const float4*)(p.adc[y] + (size_t)di * 8);
    float4 s0 = __ldg(&sp[0]), s1 = __ldg(&sp[1]);
    float4 d0 = __ldg(&dp[0]), d1 = __ldg(&dp[1]);
    float v[8] = {s0.x + d0.x, s0.y + d0.y, s0.z + d0.z, s0.w + d0.w,
                  s1.x + d1.x, s1.y + d1.y, s1.z + d1.z, s1.w + d1.w};
#pragma unroll
    for (int i = 0; i < 8; i++) {
        float a = v[i];
        a = (a >= 0.f) ? a : 0.2f * a;
        v[i] = __expf(a);
    }
    float4 e0 = make_float4(v[0], v[1], v[2], v[3]);
    float4 e1 = make_float4(v[4], v[5], v[6], v[7]);
    ((float4*)p.escr[y])[(size_t)e * 2]     = e0;
    ((float4*)p.escr[y])[(size_t)e * 2 + 1] = e1;
    atomic_add_f4((float4*)(p.den[y] + (size_t)di * 8),     e0);
    atomic_add_f4((float4*)(p.den[y] + (size_t)di * 8) + 1, e1);
}

// ----------------------------- edge pass B (all edge types, blockIdx.y) -----------
struct PB {
    const int* ei[3];
    const float* xs[3];
    const float* escr[3];
    const float* den[3];
    float* agg[3];
};

__global__ void passB_k(PB p)
{
    const int y = blockIdx.y;
    const int gt = blockIdx.x * blockDim.x + threadIdx.x;
    const int e = gt >> 5;
    if (e >= EE) return;
    const int lane = gt & 31;
    const int* ei = p.ei[y];
    const int si = __ldg(&ei[e]);
    const int di = __ldg(&ei[EE + e]);
    const int h = lane >> 2;
    const float w = __ldg(&p.escr[y][(size_t)e * 8 + h]) /
                    (__ldg(&p.den[y][(size_t)di * 8 + h]) + 1e-16f);
    float4 v = __ldg(((const float4*)p.xs[y]) + (size_t)si * 32 + lane);
    v.x *= w; v.y *= w; v.z *= w; v.w *= w;
    atomic_add_f4(((float4*)p.agg[y]) + (size_t)di * 32 + lane, v);
}

// ----------------------------- semantic attention weights (M=2) --------------------
__global__ void sem_attn_k(const float* __restrict__ colsum, const float* __restrict__ q,
                           float* __restrict__ attn)
{
    __shared__ float r0[128], r1[128];
    const int t = threadIdx.x;
    const float qv = q[t];
    r0[t] = qv * colsum[t];
    r1[t] = qv * colsum[128 + t];
    __syncthreads();
    for (int s = 64; s > 0; s >>= 1) {
        if (t < s) { r0[t] += r0[t + s]; r1[t] += r1[t + s]; }
        __syncthreads();
    }
    if (t == 0) {
        const float s0 = r0[0] / (float)NP;
        const float s1 = r1[0] / (float)NP;
        const float m = fmaxf(s0, s1);
        const float e0 = __expf(s0 - m), e1 = __expf(s1 - m);
        const float inv = 1.f / (e0 + e1);
        attn[0] = e0 * inv;
        attn[1] = e1 * inv;
    }
}

// ----------------------------- combine (layer-0): pap = a0*relu(s0)+a1*relu(s1) ----
__global__ void combine_k(float4* __restrict__ out, const float4* __restrict__ s0,
                          const float4* __restrict__ s1, const float* __restrict__ attn,
                          int n4)
{
    const int i = blockIdx.x * blockDim.x + threadIdx.x;
    if (i >= n4) return;
    const float a0 = __ldg(&attn[0]);
    const float a1 = __ldg(&attn[1]);
    float4 x = __ldg(&s0[i]);
    float4 y = __ldg(&s1[i]);
    x.x = fmaxf(x.x, 0.f); x.y = fmaxf(x.y, 0.f);
    x.z = fmaxf(x.z, 0.f); x.w = fmaxf(x.w, 0.f);
    y.x = fmaxf(y.x, 0.f); y.y = fmaxf(y.y, 0.f);
    y.z = fmaxf(y.z, 0.f); y.w = fmaxf(y.w, 0.f);
    out[i] = make_float4(a0 * x.x + a1 * y.x, a0 * x.y + a1 * y.y,
                         a0 * x.z + a1 * y.z, a0 * x.w + a1 * y.w);
}

// ----------------------------- final linear (fused layer-1 combine) ----------------
__global__ __launch_bounds__(256)
void final_lin_k(const float* __restrict__ s0, const float* __restrict__ s1,
                 const float* __restrict__ attn, const float* __restrict__ W,
                 const float* __restrict__ b, float* __restrict__ out)
{
    __shared__ float Ws[128 * NCLS];
    for (int i = threadIdx.x; i < 128 * NCLS; i += blockDim.x) Ws[i] = W[i];
    __syncthreads();
    const int n = blockIdx.x * blockDim.x + threadIdx.x;
    if (n >= NP) return;
    const float a0 = __ldg(&attn[0]);
    const float a1 = __ldg(&attn[1]);
    float acc[NCLS];
#pragma unroll
    for (int c = 0; c < NCLS; c++) acc[c] = __ldg(&b[c]);
    const float4* x0 = (const float4*)(s0 + (size_t)n * 128);
    const float4* x1 = (const float4*)(s1 + (size_t)n * 128);
#pragma unroll
    for (int k4 = 0; k4 < 32; k4++) {
        float4 u = __ldg(&x0[k4]);
        float4 v = __ldg(&x1[k4]);
        const float xs[4] = {
            a0 * fmaxf(u.x, 0.f) + a1 * fmaxf(v.x, 0.f),
            a0 * fmaxf(u.y, 0.f) + a1 * fmaxf(v.y, 0.f),
            a0 * fmaxf(u.z, 0.f) + a1 * fmaxf(v.z, 0.f),
            a0 * fmaxf(u.w, 0.f) + a1 * fmaxf(v.w, 0.f)};
#pragma unroll
        for (int uu = 0; uu < 4; uu++) {
            const int k = k4 * 4 + uu;
#pragma unroll
            for (int c = 0; c < NCLS; c++)
                acc[c] = fmaf(xs[uu], Ws[k * NCLS + c], acc[c]);
        }
    }
    float4* op = (float4*)(out + (size_t)n * NCLS);
#pragma unroll
    for (int c4 = 0; c4 < 4; c4++)
        op[c4] = make_float4(acc[c4 * 4], acc[c4 * 4 + 1], acc[c4 * 4 + 2], acc[c4 * 4 + 3]);
}

// ----------------------------- host orchestration ----------------------------------
extern "C" void kernel_launch(void* const* d_in, const int* in_sizes, int n_in,
                              void* d_out, int out_size)
{
    const float* x_author = (const float*)d_in[0];
    const float* x_paper  = (const float*)d_in[1];
    const float* Wa       = (const float*)d_in[2];
    const float* proj_w   = (const float*)d_in[3];
    const float* proj_b   = (const float*)d_in[4];
    const float* att_src  = (const float*)d_in[5];
    const float* att_dst  = (const float*)d_in[6];
    const float* klin_w   = (const float*)d_in[7];
    const float* klin_b   = (const float*)d_in[8];
    const float* q        = (const float*)d_in[9];
    const float* lin_w    = (const float*)d_in[10];
    const float* lin_b    = (const float*)d_in[11];
    const int*   ei_w     = (const int*)d_in[12];
    const int*   ei_wb    = (const int*)d_in[13];
    const int*   ei_c     = (const int*)d_in[14];
    float* out = (float*)d_out;

    float *arena, *aggA, *auth0, *pap, *xa, *xp;
    float *escr0, *escr1, *escr2;
    float *sa0, *sa1, *sp0, *sp1, *sp2, *sp3, *attn, *zb;
    cudaGetSymbolAddress((void**)&arena, g_arena);
    cudaGetSymbolAddress((void**)&aggA, g_aggA);
    cudaGetSymbolAddress((void**)&auth0, g_auth0);
    cudaGetSymbolAddress((void**)&pap, g_pap);
    cudaGetSymbolAddress((void**)&xa, g_xa);
    cudaGetSymbolAddress((void**)&xp, g_xp);
    cudaGetSymbolAddress((void**)&escr0, g_escr0);
    cudaGetSymbolAddress((void**)&escr1, g_escr1);
    cudaGetSymbolAddress((void**)&escr2, g_escr2);
    cudaGetSymbolAddress((void**)&sa0, g_sa0);
    cudaGetSymbolAddress((void**)&sa1, g_sa1);
    cudaGetSymbolAddress((void**)&sp0, g_sp0);
    cudaGetSymbolAddress((void**)&sp1, g_sp1);
    cudaGetSymbolAddress((void**)&sp2, g_sp2);
    cudaGetSymbolAddress((void**)&sp3, g_sp3);
    cudaGetSymbolAddress((void**)&attn, g_attn);
    cudaGetSymbolAddress((void**)&zb, g_zb);

    float* den0 = arena + AR_DEN0;
    float* den1 = arena + NP * 8;
    float* den2 = arena + 2 * NP * 8;
    float* aggP0 = arena + AR_AGGP0;
    float* aggP1 = arena + AR_AGGP1;
    float* colsum = arena + AR_COLSUM;

    // author raw projection: [20000,64] @ [64,128]  (no bias, no scores)
    {
        SCSet sc; sc.n = 0;
        gemm128<false><<<(NA + 127) / 128, 256>>>(x_author, Wa, zb, auth0, NA, 64, sc);
    }

    // =============================== layer 0 ===============================
    cudaMemsetAsync(arena, 0, (size_t)AR_TOTAL * sizeof(float));
    cudaMemsetAsync(aggA, 0, (size_t)NA * HID * sizeof(float));

    {   // author projection + scores (writes-src, written_by-dst)
        SCSet sc; sc.n = 2;
        sc.s[0] = { att_src + 0 * 128, sa0 };
        sc.s[1] = { att_dst + 1 * 128, sa1 };
        gemm128<false><<<(NA + 127) / 128, 256>>>(
            auth0, proj_w, proj_b, xa, NA, 128, sc);
    }
    {   // paper projection + scores (writes-dst, wb-src, cites-src, cites-dst)
        SCSet sc; sc.n = 4;
        sc.s[0] = { att_dst + 0 * 128, sp0 };
        sc.s[1] = { att_src + 1 * 128, sp1 };
        sc.s[2] = { att_src + 2 * 128, sp2 };
        sc.s[3] = { att_dst + 2 * 128, sp3 };
        gemm128<false><<<(NP + 127) / 128, 256>>>(
            x_paper, proj_w + (size_t)128 * 128, proj_b + 128, xp, NP, 128, sc);
    }
    {
        PA pa;
        pa.ei[0] = ei_w;  pa.asc[0] = sa0; pa.adc[0] = sp0; pa.escr[0] = escr0; pa.den[0] = den0;
        pa.ei[1] = ei_wb; pa.asc[1] = sp1; pa.adc[1] = sa1; pa.escr[1] = escr1; pa.den[1] = den1;
        pa.ei[2] = ei_c;  pa.asc[2] = sp2; pa.adc[2] = sp3; pa.escr[2] = escr2; pa.den[2] = den2;
        passA_k<<<dim3((EE + 255) / 256, 3), 256>>>(pa);

        PB pb;
        pb.ei[0] = ei_w;  pb.xs[0] = xa; pb.escr[0] = escr0; pb.den[0] = den0; pb.agg[0] = aggP0;
        pb.ei[1] = ei_wb; pb.xs[1] = xp; pb.escr[1] = escr1; pb.den[1] = den1; pb.agg[1] = aggA;
        pb.ei[2] = ei_c;  pb.xs[2] = xp; pb.escr[2] = escr2; pb.den[2] = den2; pb.agg[2] = aggP1;
        passB_k<<<dim3((EE * 32 + 255) / 256, 3), 256>>>(pb);
    }
    gemm_tanh<<<dim3((NP + 127) / 128, 2), 256>>>(aggP0, aggP1, klin_w, klin_b, colsum, NP);
    sem_attn_k<<<1, 128>>>(colsum, q, attn);
    combine_k<<<(NP * 32 + 255) / 256, 256>>>(
        (float4*)pap, (const float4*)aggP0, (const float4*)aggP1, attn, NP * 32);

    // =============================== layer 1 ===============================
    // (written_by aggregation is dead at the last layer: author output unused)
    cudaMemsetAsync(arena, 0, (size_t)AR_TOTAL * sizeof(float));

    {   // author projection (RELU on input aggA) + score (writes-src)
        SCSet sc; sc.n = 1;
        sc.s[0] = { att_src + 3 * 128, sa0 };
        gemm128<true><<<(NA + 127) / 128, 256>>>(
            aggA, proj_w + (size_t)2 * 128 * 128, proj_b + 2 * 128, xa, NA, 128, sc);
    }
    {   // paper projection + scores (writes-dst, cites-src, cites-dst)
        SCSet sc; sc.n = 3;
        sc.s[0] = { att_dst + 3 * 128, sp0 };
        sc.s[1] = { att_src + 5 * 128, sp2 };
        sc.s[2] = { att_dst + 5 * 128, sp3 };
        gemm128<false><<<(NP + 127) / 128, 256>>>(
            pap, proj_w + (size_t)3 * 128 * 128, proj_b + 3 * 128, xp, NP, 128, sc);
    }
    {
        PA pa;
        pa.ei[0] = ei_w; pa.asc[0] = sa0; pa.adc[0] = sp0; pa.escr[0] = escr0; pa.den[0] = den0;
        pa.ei[1] = ei_c; pa.asc[1] = sp2; pa.adc[1] = sp3; pa.escr[1] = escr2; pa.den[1] = den2;
        pa.ei[2] = pa.ei[1]; pa.asc[2] = pa.asc[1]; pa.adc[2] = pa.adc[1];
        pa.escr[2] = pa.escr[1]; pa.den[2] = pa.den[1];
        passA_k<<<dim3((EE + 255) / 256, 2), 256>>>(pa);

        PB pb;
        pb.ei[0] = ei_w; pb.xs[0] = xa; pb.escr[0] = escr0; pb.den[0] = den0; pb.agg[0] = aggP0;
        pb.ei[1] = ei_c; pb.xs[1] = xp; pb.escr[1] = escr2; pb.den[1] = den2; pb.agg[1] = aggP1;
        pb.ei[2] = pb.ei[1]; pb.xs[2] = pb.xs[1]; pb.escr[2] = pb.escr[1];
        pb.den[2] = pb.den[1]; pb.agg[2] = pb.agg[1];
        passB_k<<<dim3((EE * 32 + 255) / 256, 2), 256>>>(pb);
    }
    gemm_tanh<<<dim3((NP + 127) / 128, 2), 256>>>(
        aggP0, aggP1, klin_w + (size_t)128 * 128, klin_b + 128, colsum, NP);
    sem_attn_k<<<1, 128>>>(colsum, q + 128, attn);

    // final linear with fused layer-1 combine
    final_lin_k<<<(NP + 255) / 256, 256>>>(aggP0, aggP1, attn, lin_w, lin_b, out);
}